// round 1
// baseline (speedup 1.0000x reference)
#include <cuda_runtime.h>
#include <math.h>

#define NN   50000
#define EE   800000
#define ETOT 850000
#define HIDD 256
#define FFND 1024

// ---------------- scratch (static device globals; no allocs) ----------------
__device__ float    g_xsrc[(size_t)NN * HIDD];
__device__ float    g_xdst[(size_t)NN * HIDD];
__device__ float    g_h   [(size_t)NN * HIDD];
__device__ float    g_agg [(size_t)NN * HIDD];
__device__ float    g_mid [(size_t)NN * FFND];
__device__ float    g_ssrc[NN * 16];   // [n][t][h]
__device__ float    g_sdst[NN * 16];
__device__ unsigned g_menc[NN * 8];
__device__ float    g_denom[NN * 8];
__device__ float    g_alpha[(size_t)ETOT * 8];

// monotone float<->uint encoding for atomicMax on floats
__device__ __forceinline__ unsigned fenc(float f) {
    unsigned b = __float_as_uint(f);
    return (b >> 31) ? ~b : (b | 0x80000000u);
}
__device__ __forceinline__ float fdec(unsigned u) {
    return (u >> 31) ? __uint_as_float(u & 0x7fffffffu) : __uint_as_float(~u);
}

__device__ __forceinline__ void red_add_v4(float* p, float a, float b, float c, float d) {
    asm volatile("red.global.add.v4.f32 [%0], {%1,%2,%3,%4};"
                 :: "l"(p), "f"(a), "f"(b), "f"(c), "f"(d) : "memory");
}

// ---------------- SGEMM: C[M,Nd] = A[M,K] * B[Nd,K]^T, EPI: 0 none, 1 bias+gelu, 2 bias ----
template<int EPI>
__global__ void __launch_bounds__(256) sgemm_kernel(
    const float* __restrict__ A, const float* __restrict__ B,
    float* __restrict__ C, const float* __restrict__ bias,
    int M, int Nd, int K)
{
    __shared__ float As[8][128];
    __shared__ float Bs[8][128];
    const int bm = blockIdx.y * 128;
    const int bn = blockIdx.x * 128;
    const int tid = threadIdx.x;
    const int tr = (tid >> 4) << 3;   // 0..120
    const int tc = (tid & 15) << 3;   // 0..120
    const int lrow = tid >> 1;        // 0..127
    const int lcol = (tid & 1) << 2;  // 0 or 4
    const float* Aptr = A + (size_t)(bm + lrow) * K + lcol;
    const float* Bptr = B + (size_t)(bn + lrow) * K + lcol;
    const bool a_ok = (bm + lrow) < M;

    float acc[8][8];
#pragma unroll
    for (int i = 0; i < 8; i++)
#pragma unroll
        for (int j = 0; j < 8; j++) acc[i][j] = 0.f;

    for (int k0 = 0; k0 < K; k0 += 8) {
        float4 av = make_float4(0.f, 0.f, 0.f, 0.f);
        if (a_ok) av = *(const float4*)(Aptr + k0);
        float4 bv = *(const float4*)(Bptr + k0);
        As[lcol + 0][lrow] = av.x; As[lcol + 1][lrow] = av.y;
        As[lcol + 2][lrow] = av.z; As[lcol + 3][lrow] = av.w;
        Bs[lcol + 0][lrow] = bv.x; Bs[lcol + 1][lrow] = bv.y;
        Bs[lcol + 2][lrow] = bv.z; Bs[lcol + 3][lrow] = bv.w;
        __syncthreads();
#pragma unroll
        for (int kk = 0; kk < 8; kk++) {
            float ar[8], br[8];
            *(float4*)&ar[0] = *(const float4*)&As[kk][tr];
            *(float4*)&ar[4] = *(const float4*)&As[kk][tr + 4];
            *(float4*)&br[0] = *(const float4*)&Bs[kk][tc];
            *(float4*)&br[4] = *(const float4*)&Bs[kk][tc + 4];
#pragma unroll
            for (int i = 0; i < 8; i++)
#pragma unroll
                for (int j = 0; j < 8; j++) acc[i][j] += ar[i] * br[j];
        }
        __syncthreads();
    }

    float bcol[8];
    if (EPI) {
        *(float4*)&bcol[0] = *(const float4*)&bias[bn + tc];
        *(float4*)&bcol[4] = *(const float4*)&bias[bn + tc + 4];
    }
#pragma unroll
    for (int i = 0; i < 8; i++) {
        int m = bm + tr + i;
        if (m < M) {
            float vals[8];
#pragma unroll
            for (int j = 0; j < 8; j++) {
                float v = acc[i][j];
                if (EPI) v += bcol[j];
                if (EPI == 1) v = 0.5f * v * (1.f + erff(v * 0.70710678118654752f));
                vals[j] = v;
            }
            float* Cp = C + (size_t)m * Nd + bn + tc;
            *(float4*)Cp       = *(float4*)&vals[0];
            *(float4*)(Cp + 4) = *(float4*)&vals[4];
        }
    }
}

// ---------------- init accumulators ----------------
__global__ void init_kernel() {
    int i = blockIdx.x * blockDim.x + threadIdx.x;
    if (i < NN * HIDD) g_agg[i] = 0.f;
    if (i < NN * 8) { g_menc[i] = 0u; g_denom[i] = 0.f; }
}

// ---------------- per-node attention dot precompute: s[n,t,h] ----------------
__global__ void node_prep_kernel(const float* __restrict__ att_src,
                                 const float* __restrict__ att_dst) {
    int i = blockIdx.x * blockDim.x + threadIdx.x;   // over NN*16
    if (i >= NN * 16) return;
    int n = i >> 4, th = i & 15;
    int t = th >> 3, h = th & 7;
    const float4* xs = (const float4*)&g_xsrc[(size_t)n * HIDD + h * 32];
    const float4* xd = (const float4*)&g_xdst[(size_t)n * HIDD + h * 32];
    const float4* as = (const float4*)&att_src[(t * 8 + h) * 32];
    const float4* ad = (const float4*)&att_dst[(t * 8 + h) * 32];
    float ss = 0.f, sd = 0.f;
#pragma unroll
    for (int q = 0; q < 8; q++) {
        float4 a = xs[q], b = as[q];
        ss += a.x * b.x + a.y * b.y + a.z * b.z + a.w * b.w;
        float4 c = xd[q], d = ad[q];
        sd += c.x * d.x + c.y * d.y + c.z * d.z + c.w * d.w;
    }
    g_ssrc[i] = ss;
    g_sdst[i] = sd;
}

// ---------------- edge pass A: alpha + leaky relu + segment max ----------------
__global__ void edgeA_kernel(const int* __restrict__ ei, const int* __restrict__ et) {
    int e = blockIdx.x * blockDim.x + threadIdx.x;
    if (e >= ETOT) return;
    int s, d, t;
    if (e < EE) { s = ei[e]; d = ei[EE + e]; t = et[e]; }
    else        { s = d = e - EE; t = 0; }
    float4 s0 = *(const float4*)&g_ssrc[s * 16 + t * 8];
    float4 s1 = *(const float4*)&g_ssrc[s * 16 + t * 8 + 4];
    float4 d0 = *(const float4*)&g_sdst[d * 16 + t * 8];
    float4 d1 = *(const float4*)&g_sdst[d * 16 + t * 8 + 4];
    float al[8] = { s0.x + d0.x, s0.y + d0.y, s0.z + d0.z, s0.w + d0.w,
                    s1.x + d1.x, s1.y + d1.y, s1.z + d1.z, s1.w + d1.w };
#pragma unroll
    for (int h = 0; h < 8; h++) al[h] = (al[h] >= 0.f) ? al[h] : 0.2f * al[h];
    float* ap = &g_alpha[(size_t)e * 8];
    *(float4*)ap       = make_float4(al[0], al[1], al[2], al[3]);
    *(float4*)(ap + 4) = make_float4(al[4], al[5], al[6], al[7]);
#pragma unroll
    for (int h = 0; h < 8; h++) atomicMax(&g_menc[d * 8 + h], fenc(al[h]));
}

// ---------------- edge pass B: exp(alpha-m) and denom ----------------
__global__ void edgeB_kernel(const int* __restrict__ ei) {
    int e = blockIdx.x * blockDim.x + threadIdx.x;
    if (e >= ETOT) return;
    int d = (e < EE) ? ei[EE + e] : (e - EE);
    float* ap = &g_alpha[(size_t)e * 8];
    float4 a0 = *(const float4*)ap;
    float4 a1 = *(const float4*)(ap + 4);
    uint4 m0 = *(const uint4*)&g_menc[d * 8];
    uint4 m1 = *(const uint4*)&g_menc[d * 8 + 4];
    float p[8];
    p[0] = expf(a0.x - fdec(m0.x)); p[1] = expf(a0.y - fdec(m0.y));
    p[2] = expf(a0.z - fdec(m0.z)); p[3] = expf(a0.w - fdec(m0.w));
    p[4] = expf(a1.x - fdec(m1.x)); p[5] = expf(a1.y - fdec(m1.y));
    p[6] = expf(a1.z - fdec(m1.z)); p[7] = expf(a1.w - fdec(m1.w));
    *(float4*)ap       = make_float4(p[0], p[1], p[2], p[3]);
    *(float4*)(ap + 4) = make_float4(p[4], p[5], p[6], p[7]);
#pragma unroll
    for (int h = 0; h < 8; h++) atomicAdd(&g_denom[d * 8 + h], p[h]);
}

// ---------------- edge pass C: message scatter (one warp per edge) ----------------
__global__ void __launch_bounds__(256) edgeC_kernel(const int* __restrict__ ei,
                                                    const float* __restrict__ ew) {
    int e = (blockIdx.x * blockDim.x + threadIdx.x) >> 5;
    int lane = threadIdx.x & 31;
    if (e >= ETOT) return;
    int s, d; float w;
    if (e < EE) { s = ei[e]; d = ei[EE + e]; w = ew[e]; }
    else        { s = d = e - EE; w = 1.f; }
    float cv = 0.f;
    if (lane < 8) cv = g_alpha[(size_t)e * 8 + lane] / g_denom[d * 8 + lane] * w;
    float c1 = __shfl_sync(0xffffffffu, cv, lane >> 3);        // heads 0..3
    float c2 = __shfl_sync(0xffffffffu, cv, 4 + (lane >> 3));  // heads 4..7
    const float4* xs = (const float4*)&g_xsrc[(size_t)s * HIDD];
    float4 v1 = xs[lane];
    float4 v2 = xs[32 + lane];
    float* op = &g_agg[(size_t)d * HIDD];
    red_add_v4(op + lane * 4,       v1.x * c1, v1.y * c1, v1.z * c1, v1.w * c1);
    red_add_v4(op + 128 + lane * 4, v2.x * c2, v2.y * c2, v2.z * c2, v2.w * c2);
}

// ---------------- LayerNorm (warp per row): out = LN(a + b + colbias?) ----------------
__global__ void ln_kernel(const float* __restrict__ a, const float* __restrict__ b,
                          const float* __restrict__ colbias,
                          const float* __restrict__ g, const float* __restrict__ beta,
                          float* __restrict__ out) {
    int row = (blockIdx.x * blockDim.x + threadIdx.x) >> 5;
    int lane = threadIdx.x & 31;
    if (row >= NN) return;
    size_t base = (size_t)row * HIDD;
    float4 a0 = *(const float4*)&a[base + lane * 4];
    float4 a1 = *(const float4*)&a[base + 128 + lane * 4];
    float4 b0 = *(const float4*)&b[base + lane * 4];
    float4 b1 = *(const float4*)&b[base + 128 + lane * 4];
    float v[8] = { a0.x + b0.x, a0.y + b0.y, a0.z + b0.z, a0.w + b0.w,
                   a1.x + b1.x, a1.y + b1.y, a1.z + b1.z, a1.w + b1.w };
    if (colbias) {
        float4 c0 = *(const float4*)&colbias[lane * 4];
        float4 c1 = *(const float4*)&colbias[128 + lane * 4];
        v[0] += c0.x; v[1] += c0.y; v[2] += c0.z; v[3] += c0.w;
        v[4] += c1.x; v[5] += c1.y; v[6] += c1.z; v[7] += c1.w;
    }
    float s = 0.f, s2 = 0.f;
#pragma unroll
    for (int q = 0; q < 8; q++) { s += v[q]; s2 += v[q] * v[q]; }
#pragma unroll
    for (int off = 16; off; off >>= 1) {
        s  += __shfl_xor_sync(0xffffffffu, s, off);
        s2 += __shfl_xor_sync(0xffffffffu, s2, off);
    }
    float mu = s * (1.f / 256.f);
    float var = s2 * (1.f / 256.f) - mu * mu;
    float r = rsqrtf(var + 1e-5f);
    float4 g0 = *(const float4*)&g[lane * 4];
    float4 g1 = *(const float4*)&g[128 + lane * 4];
    float4 e0 = *(const float4*)&beta[lane * 4];
    float4 e1 = *(const float4*)&beta[128 + lane * 4];
    float o[8];
    o[0] = (v[0] - mu) * r * g0.x + e0.x; o[1] = (v[1] - mu) * r * g0.y + e0.y;
    o[2] = (v[2] - mu) * r * g0.z + e0.z; o[3] = (v[3] - mu) * r * g0.w + e0.w;
    o[4] = (v[4] - mu) * r * g1.x + e1.x; o[5] = (v[5] - mu) * r * g1.y + e1.y;
    o[6] = (v[6] - mu) * r * g1.z + e1.z; o[7] = (v[7] - mu) * r * g1.w + e1.w;
    *(float4*)&out[base + lane * 4]       = make_float4(o[0], o[1], o[2], o[3]);
    *(float4*)&out[base + 128 + lane * 4] = make_float4(o[4], o[5], o[6], o[7]);
}

// ---------------- launch ----------------
extern "C" void kernel_launch(void* const* d_in, const int* in_sizes, int n_in,
                              void* d_out, int out_size) {
    const float* x       = (const float*)d_in[0];
    const int*   ei      = (const int*)  d_in[1];
    const int*   et      = (const int*)  d_in[2];
    const float* ew      = (const float*)d_in[3];
    const float* Wsrc    = (const float*)d_in[4];
    const float* Wdst    = (const float*)d_in[5];
    const float* att_src = (const float*)d_in[6];
    const float* att_dst = (const float*)d_in[7];
    const float* bias    = (const float*)d_in[8];
    const float* ln1g    = (const float*)d_in[9];
    const float* ln1b    = (const float*)d_in[10];
    const float* ln2g    = (const float*)d_in[11];
    const float* ln2b    = (const float*)d_in[12];
    const float* W1      = (const float*)d_in[13];
    const float* b1      = (const float*)d_in[14];
    const float* W2      = (const float*)d_in[15];
    const float* b2      = (const float*)d_in[16];
    float* out = (float*)d_out;

    float *p_xsrc, *p_xdst, *p_h, *p_agg, *p_mid;
    cudaGetSymbolAddress((void**)&p_xsrc, g_xsrc);
    cudaGetSymbolAddress((void**)&p_xdst, g_xdst);
    cudaGetSymbolAddress((void**)&p_h,    g_h);
    cudaGetSymbolAddress((void**)&p_agg,  g_agg);
    cudaGetSymbolAddress((void**)&p_mid,  g_mid);

    const int TPB = 256;
    dim3 gemm_grid_h((HIDD + 127) / 128, (NN + 127) / 128);  // Nd=256
    dim3 gemm_grid_f((FFND + 127) / 128, (NN + 127) / 128);  // Nd=1024

    init_kernel<<<(NN * HIDD + TPB - 1) / TPB, TPB>>>();

    sgemm_kernel<0><<<gemm_grid_h, TPB>>>(x, Wsrc, p_xsrc, nullptr, NN, HIDD, HIDD);
    sgemm_kernel<0><<<gemm_grid_h, TPB>>>(x, Wdst, p_xdst, nullptr, NN, HIDD, HIDD);

    node_prep_kernel<<<(NN * 16 + TPB - 1) / TPB, TPB>>>(att_src, att_dst);

    edgeA_kernel<<<(ETOT + TPB - 1) / TPB, TPB>>>(ei, et);
    edgeB_kernel<<<(ETOT + TPB - 1) / TPB, TPB>>>(ei);
    edgeC_kernel<<<((size_t)ETOT * 32 + TPB - 1) / TPB, TPB>>>(ei, ew);

    // h = LN1(agg + bias + x)
    ln_kernel<<<(NN * 32 + TPB - 1) / TPB, TPB>>>(p_agg, x, bias, ln1g, ln1b, p_h);

    // FFN
    sgemm_kernel<1><<<gemm_grid_f, TPB>>>(p_h, W1, p_mid, b1, NN, FFND, HIDD);
    sgemm_kernel<2><<<gemm_grid_h, TPB>>>(p_mid, W2, p_agg, b2, NN, HIDD, FFND);

    // out = LN2(h + ffn_out)
    ln_kernel<<<(NN * 32 + TPB - 1) / TPB, TPB>>>(p_agg, p_h, nullptr, ln2g, ln2b, out);
}

// round 2
// speedup vs baseline: 1.0272x; 1.0272x over previous
#include <cuda_runtime.h>
#include <math.h>

#define NN   50000
#define EE   800000
#define ETOT 850000
#define HIDD 256
#define FFND 1024

// ---------------- scratch (static device globals; no allocs) ----------------
__device__ float    g_xsrc[(size_t)NN * HIDD];
__device__ float    g_xdst[(size_t)NN * HIDD];
__device__ float    g_h   [(size_t)NN * HIDD];
__device__ float    g_agg [(size_t)NN * HIDD];
__device__ float    g_mid [(size_t)NN * FFND];
__device__ float    g_ssrc[NN * 16];   // [n][t][h]
__device__ float    g_sdst[NN * 16];
__device__ unsigned g_menc[NN * 8];
__device__ float    g_denom[NN * 8];
__device__ float    g_alpha[(size_t)ETOT * 8];

// monotone float<->uint encoding for atomicMax on floats
__device__ __forceinline__ unsigned fenc(float f) {
    unsigned b = __float_as_uint(f);
    return (b >> 31) ? ~b : (b | 0x80000000u);
}
__device__ __forceinline__ float fdec(unsigned u) {
    return (u >> 31) ? __uint_as_float(u & 0x7fffffffu) : __uint_as_float(~u);
}

__device__ __forceinline__ void red_add_v4(float* p, float a, float b, float c, float d) {
    asm volatile("red.global.add.v4.f32 [%0], {%1,%2,%3,%4};"
                 :: "l"(p), "f"(a), "f"(b), "f"(c), "f"(d) : "memory");
}

// ---------------- packed f32x2 helpers (FFMA2 — 2x fp32 rate on sm_103a) ----
__device__ __forceinline__ unsigned long long pack2(float lo, float hi) {
    unsigned long long r;
    asm("mov.b64 %0, {%1,%2};" : "=l"(r) : "f"(lo), "f"(hi));
    return r;
}
__device__ __forceinline__ unsigned long long ffma2(unsigned long long a,
                                                    unsigned long long b,
                                                    unsigned long long c) {
    unsigned long long d;
    asm("fma.rn.f32x2 %0, %1, %2, %3;" : "=l"(d) : "l"(a), "l"(b), "l"(c));
    return d;
}
__device__ __forceinline__ float2 unpack2(unsigned long long v) {
    float2 f;
    asm("mov.b64 {%0,%1}, %2;" : "=f"(f.x), "=f"(f.y) : "l"(v));
    return f;
}

// ---------------- SGEMM (FFMA2): C[M,Nd] = A[M,K]*B[Nd,K]^T, EPI: 0 none, 1 bias+gelu, 2 bias
template<int EPI>
__global__ void __launch_bounds__(256, 2) sgemm_kernel(
    const float* __restrict__ A, const float* __restrict__ B,
    float* __restrict__ C, const float* __restrict__ bias,
    int M, int Nd, int K)
{
    __shared__ float As[16][128];
    __shared__ float Bs[16][128];
    const int bm = blockIdx.y * 128;
    const int bn = blockIdx.x * 128;
    const int tid = threadIdx.x;
    const int tr = (tid >> 4) << 3;   // 0..120 (row base of 8)
    const int tc = (tid & 15) << 3;   // 0..120 (col base of 8)
    const int lrow = tid >> 1;        // 0..127
    const int lcol = (tid & 1) << 3;  // 0 or 8
    const float* Aptr = A + (size_t)(bm + lrow) * K + lcol;
    const float* Bptr = B + (size_t)(bn + lrow) * K + lcol;
    const bool a_ok = (bm + lrow) < M;

    unsigned long long acc[4][8];   // row-pairs (tr+2ip, tr+2ip+1) x 8 cols
#pragma unroll
    for (int i = 0; i < 4; i++)
#pragma unroll
        for (int j = 0; j < 8; j++) acc[i][j] = 0ull;

    for (int k0 = 0; k0 < K; k0 += 16) {
        float4 av0 = make_float4(0.f, 0.f, 0.f, 0.f), av1 = av0;
        if (a_ok) {
            av0 = *(const float4*)(Aptr + k0);
            av1 = *(const float4*)(Aptr + k0 + 4);
        }
        float4 bv0 = *(const float4*)(Bptr + k0);
        float4 bv1 = *(const float4*)(Bptr + k0 + 4);
        As[lcol + 0][lrow] = av0.x; As[lcol + 1][lrow] = av0.y;
        As[lcol + 2][lrow] = av0.z; As[lcol + 3][lrow] = av0.w;
        As[lcol + 4][lrow] = av1.x; As[lcol + 5][lrow] = av1.y;
        As[lcol + 6][lrow] = av1.z; As[lcol + 7][lrow] = av1.w;
        Bs[lcol + 0][lrow] = bv0.x; Bs[lcol + 1][lrow] = bv0.y;
        Bs[lcol + 2][lrow] = bv0.z; Bs[lcol + 3][lrow] = bv0.w;
        Bs[lcol + 4][lrow] = bv1.x; Bs[lcol + 5][lrow] = bv1.y;
        Bs[lcol + 6][lrow] = bv1.z; Bs[lcol + 7][lrow] = bv1.w;
        __syncthreads();
#pragma unroll
        for (int kk = 0; kk < 16; kk++) {
            float4 a0 = *(const float4*)&As[kk][tr];
            float4 a1 = *(const float4*)&As[kk][tr + 4];
            float4 b0 = *(const float4*)&Bs[kk][tc];
            float4 b1 = *(const float4*)&Bs[kk][tc + 4];
            unsigned long long ap[4];
            ap[0] = pack2(a0.x, a0.y); ap[1] = pack2(a0.z, a0.w);
            ap[2] = pack2(a1.x, a1.y); ap[3] = pack2(a1.z, a1.w);
            unsigned long long bd[8];
            bd[0] = pack2(b0.x, b0.x); bd[1] = pack2(b0.y, b0.y);
            bd[2] = pack2(b0.z, b0.z); bd[3] = pack2(b0.w, b0.w);
            bd[4] = pack2(b1.x, b1.x); bd[5] = pack2(b1.y, b1.y);
            bd[6] = pack2(b1.z, b1.z); bd[7] = pack2(b1.w, b1.w);
#pragma unroll
            for (int i = 0; i < 4; i++)
#pragma unroll
                for (int j = 0; j < 8; j++)
                    acc[i][j] = ffma2(ap[i], bd[j], acc[i][j]);
        }
        __syncthreads();
    }

    float bcol[8];
    if (EPI) {
        *(float4*)&bcol[0] = *(const float4*)&bias[bn + tc];
        *(float4*)&bcol[4] = *(const float4*)&bias[bn + tc + 4];
    }
#pragma unroll
    for (int r = 0; r < 8; r++) {
        int m = bm + tr + r;
        if (m < M) {
            int ip = r >> 1, hf = r & 1;
            float vals[8];
#pragma unroll
            for (int j = 0; j < 8; j++) {
                float2 p = unpack2(acc[ip][j]);
                float v = hf ? p.y : p.x;
                if (EPI) v += bcol[j];
                if (EPI == 1) v = 0.5f * v * (1.f + erff(v * 0.70710678118654752f));
                vals[j] = v;
            }
            float* Cp = C + (size_t)m * Nd + bn + tc;
            *(float4*)Cp       = *(float4*)&vals[0];
            *(float4*)(Cp + 4) = *(float4*)&vals[4];
        }
    }
}

// ---------------- init accumulators ----------------
__global__ void init_kernel() {
    int i = blockIdx.x * blockDim.x + threadIdx.x;
    if (i < NN * HIDD) g_agg[i] = 0.f;
    if (i < NN * 8) { g_menc[i] = 0u; g_denom[i] = 0.f; }
}

// ---------------- per-node attention dot precompute: s[n,t,h] (both t per thread) ----
__global__ void node_prep_kernel(const float* __restrict__ att_src,
                                 const float* __restrict__ att_dst) {
    int i = blockIdx.x * blockDim.x + threadIdx.x;   // over NN*8
    if (i >= NN * 8) return;
    int n = i >> 3, h = i & 7;
    const float4* xs = (const float4*)&g_xsrc[(size_t)n * HIDD + h * 32];
    const float4* xd = (const float4*)&g_xdst[(size_t)n * HIDD + h * 32];
    const float4* as0 = (const float4*)&att_src[h * 32];
    const float4* as1 = (const float4*)&att_src[(8 + h) * 32];
    const float4* ad0 = (const float4*)&att_dst[h * 32];
    const float4* ad1 = (const float4*)&att_dst[(8 + h) * 32];
    float s0 = 0.f, s1 = 0.f, d0 = 0.f, d1 = 0.f;
#pragma unroll
    for (int q = 0; q < 8; q++) {
        float4 a = xs[q], c = xd[q];
        float4 b0 = as0[q], b1 = as1[q], e0 = ad0[q], e1 = ad1[q];
        s0 += a.x * b0.x + a.y * b0.y + a.z * b0.z + a.w * b0.w;
        s1 += a.x * b1.x + a.y * b1.y + a.z * b1.z + a.w * b1.w;
        d0 += c.x * e0.x + c.y * e0.y + c.z * e0.z + c.w * e0.w;
        d1 += c.x * e1.x + c.y * e1.y + c.z * e1.z + c.w * e1.w;
    }
    g_ssrc[n * 16 + h] = s0;
    g_ssrc[n * 16 + 8 + h] = s1;
    g_sdst[n * 16 + h] = d0;
    g_sdst[n * 16 + 8 + h] = d1;
}

// ---------------- edge pass A: alpha + leaky relu + segment max ----------------
__global__ void edgeA_kernel(const int* __restrict__ ei, const int* __restrict__ et) {
    int e = blockIdx.x * blockDim.x + threadIdx.x;
    if (e >= ETOT) return;
    int s, d, t;
    if (e < EE) { s = ei[e]; d = ei[EE + e]; t = et[e]; }
    else        { s = d = e - EE; t = 0; }
    float4 s0 = *(const float4*)&g_ssrc[s * 16 + t * 8];
    float4 s1 = *(const float4*)&g_ssrc[s * 16 + t * 8 + 4];
    float4 d0 = *(const float4*)&g_sdst[d * 16 + t * 8];
    float4 d1 = *(const float4*)&g_sdst[d * 16 + t * 8 + 4];
    float al[8] = { s0.x + d0.x, s0.y + d0.y, s0.z + d0.z, s0.w + d0.w,
                    s1.x + d1.x, s1.y + d1.y, s1.z + d1.z, s1.w + d1.w };
#pragma unroll
    for (int h = 0; h < 8; h++) al[h] = (al[h] >= 0.f) ? al[h] : 0.2f * al[h];
    float* ap = &g_alpha[(size_t)e * 8];
    *(float4*)ap       = make_float4(al[0], al[1], al[2], al[3]);
    *(float4*)(ap + 4) = make_float4(al[4], al[5], al[6], al[7]);
#pragma unroll
    for (int h = 0; h < 8; h++) atomicMax(&g_menc[d * 8 + h], fenc(al[h]));
}

// ---------------- edge pass B: exp(alpha-m) and denom ----------------
__global__ void edgeB_kernel(const int* __restrict__ ei) {
    int e = blockIdx.x * blockDim.x + threadIdx.x;
    if (e >= ETOT) return;
    int d = (e < EE) ? ei[EE + e] : (e - EE);
    float* ap = &g_alpha[(size_t)e * 8];
    float4 a0 = *(const float4*)ap;
    float4 a1 = *(const float4*)(ap + 4);
    uint4 m0 = *(const uint4*)&g_menc[d * 8];
    uint4 m1 = *(const uint4*)&g_menc[d * 8 + 4];
    float p[8];
    p[0] = expf(a0.x - fdec(m0.x)); p[1] = expf(a0.y - fdec(m0.y));
    p[2] = expf(a0.z - fdec(m0.z)); p[3] = expf(a0.w - fdec(m0.w));
    p[4] = expf(a1.x - fdec(m1.x)); p[5] = expf(a1.y - fdec(m1.y));
    p[6] = expf(a1.z - fdec(m1.z)); p[7] = expf(a1.w - fdec(m1.w));
    *(float4*)ap       = make_float4(p[0], p[1], p[2], p[3]);
    *(float4*)(ap + 4) = make_float4(p[4], p[5], p[6], p[7]);
#pragma unroll
    for (int h = 0; h < 8; h++) atomicAdd(&g_denom[d * 8 + h], p[h]);
}

// ---------------- edge pass C: message scatter (one warp per edge) ----------------
__global__ void __launch_bounds__(256) edgeC_kernel(const int* __restrict__ ei,
                                                    const float* __restrict__ ew) {
    int e = (blockIdx.x * blockDim.x + threadIdx.x) >> 5;
    int lane = threadIdx.x & 31;
    if (e >= ETOT) return;
    int s, d; float w;
    if (e < EE) { s = ei[e]; d = ei[EE + e]; w = ew[e]; }
    else        { s = d = e - EE; w = 1.f; }
    float cv = 0.f;
    if (lane < 8) cv = g_alpha[(size_t)e * 8 + lane] / g_denom[d * 8 + lane] * w;
    float c1 = __shfl_sync(0xffffffffu, cv, lane >> 3);        // heads 0..3
    float c2 = __shfl_sync(0xffffffffu, cv, 4 + (lane >> 3));  // heads 4..7
    const float4* xs = (const float4*)&g_xsrc[(size_t)s * HIDD];
    float4 v1 = xs[lane];
    float4 v2 = xs[32 + lane];
    float* op = &g_agg[(size_t)d * HIDD];
    red_add_v4(op + lane * 4,       v1.x * c1, v1.y * c1, v1.z * c1, v1.w * c1);
    red_add_v4(op + 128 + lane * 4, v2.x * c2, v2.y * c2, v2.z * c2, v2.w * c2);
}

// ---------------- LayerNorm (warp per row): out = LN(a + b + colbias?) ----------------
__global__ void ln_kernel(const float* __restrict__ a, const float* __restrict__ b,
                          const float* __restrict__ colbias,
                          const float* __restrict__ g, const float* __restrict__ beta,
                          float* __restrict__ out) {
    int row = (blockIdx.x * blockDim.x + threadIdx.x) >> 5;
    int lane = threadIdx.x & 31;
    if (row >= NN) return;
    size_t base = (size_t)row * HIDD;
    float4 a0 = *(const float4*)&a[base + lane * 4];
    float4 a1 = *(const float4*)&a[base + 128 + lane * 4];
    float4 b0 = *(const float4*)&b[base + lane * 4];
    float4 b1 = *(const float4*)&b[base + 128 + lane * 4];
    float v[8] = { a0.x + b0.x, a0.y + b0.y, a0.z + b0.z, a0.w + b0.w,
                   a1.x + b1.x, a1.y + b1.y, a1.z + b1.z, a1.w + b1.w };
    if (colbias) {
        float4 c0 = *(const float4*)&colbias[lane * 4];
        float4 c1 = *(const float4*)&colbias[128 + lane * 4];
        v[0] += c0.x; v[1] += c0.y; v[2] += c0.z; v[3] += c0.w;
        v[4] += c1.x; v[5] += c1.y; v[6] += c1.z; v[7] += c1.w;
    }
    float s = 0.f, s2 = 0.f;
#pragma unroll
    for (int q = 0; q < 8; q++) { s += v[q]; s2 += v[q] * v[q]; }
#pragma unroll
    for (int off = 16; off; off >>= 1) {
        s  += __shfl_xor_sync(0xffffffffu, s, off);
        s2 += __shfl_xor_sync(0xffffffffu, s2, off);
    }
    float mu = s * (1.f / 256.f);
    float var = s2 * (1.f / 256.f) - mu * mu;
    float r = rsqrtf(var + 1e-5f);
    float4 g0 = *(const float4*)&g[lane * 4];
    float4 g1 = *(const float4*)&g[128 + lane * 4];
    float4 e0 = *(const float4*)&beta[lane * 4];
    float4 e1 = *(const float4*)&beta[128 + lane * 4];
    float o[8];
    o[0] = (v[0] - mu) * r * g0.x + e0.x; o[1] = (v[1] - mu) * r * g0.y + e0.y;
    o[2] = (v[2] - mu) * r * g0.z + e0.z; o[3] = (v[3] - mu) * r * g0.w + e0.w;
    o[4] = (v[4] - mu) * r * g1.x + e1.x; o[5] = (v[5] - mu) * r * g1.y + e1.y;
    o[6] = (v[6] - mu) * r * g1.z + e1.z; o[7] = (v[7] - mu) * r * g1.w + e1.w;
    *(float4*)&out[base + lane * 4]       = make_float4(o[0], o[1], o[2], o[3]);
    *(float4*)&out[base + 128 + lane * 4] = make_float4(o[4], o[5], o[6], o[7]);
}

// ---------------- launch ----------------
extern "C" void kernel_launch(void* const* d_in, const int* in_sizes, int n_in,
                              void* d_out, int out_size) {
    const float* x       = (const float*)d_in[0];
    const int*   ei      = (const int*)  d_in[1];
    const int*   et      = (const int*)  d_in[2];
    const float* ew      = (const float*)d_in[3];
    const float* Wsrc    = (const float*)d_in[4];
    const float* Wdst    = (const float*)d_in[5];
    const float* att_src = (const float*)d_in[6];
    const float* att_dst = (const float*)d_in[7];
    const float* bias    = (const float*)d_in[8];
    const float* ln1g    = (const float*)d_in[9];
    const float* ln1b    = (const float*)d_in[10];
    const float* ln2g    = (const float*)d_in[11];
    const float* ln2b    = (const float*)d_in[12];
    const float* W1      = (const float*)d_in[13];
    const float* b1      = (const float*)d_in[14];
    const float* W2      = (const float*)d_in[15];
    const float* b2      = (const float*)d_in[16];
    float* out = (float*)d_out;

    float *p_xsrc, *p_xdst, *p_h, *p_agg, *p_mid;
    cudaGetSymbolAddress((void**)&p_xsrc, g_xsrc);
    cudaGetSymbolAddress((void**)&p_xdst, g_xdst);
    cudaGetSymbolAddress((void**)&p_h,    g_h);
    cudaGetSymbolAddress((void**)&p_agg,  g_agg);
    cudaGetSymbolAddress((void**)&p_mid,  g_mid);

    const int TPB = 256;
    dim3 gemm_grid_h((HIDD + 127) / 128, (NN + 127) / 128);  // Nd=256
    dim3 gemm_grid_f((FFND + 127) / 128, (NN + 127) / 128);  // Nd=1024

    init_kernel<<<(NN * HIDD + TPB - 1) / TPB, TPB>>>();

    sgemm_kernel<0><<<gemm_grid_h, TPB>>>(x, Wsrc, p_xsrc, nullptr, NN, HIDD, HIDD);
    sgemm_kernel<0><<<gemm_grid_h, TPB>>>(x, Wdst, p_xdst, nullptr, NN, HIDD, HIDD);

    node_prep_kernel<<<(NN * 8 + TPB - 1) / TPB, TPB>>>(att_src, att_dst);

    edgeA_kernel<<<(ETOT + TPB - 1) / TPB, TPB>>>(ei, et);
    edgeB_kernel<<<(ETOT + TPB - 1) / TPB, TPB>>>(ei);
    edgeC_kernel<<<((size_t)ETOT * 32 + TPB - 1) / TPB, TPB>>>(ei, ew);

    // h = LN1(agg + bias + x)
    ln_kernel<<<(NN * 32 + TPB - 1) / TPB, TPB>>>(p_agg, x, bias, ln1g, ln1b, p_h);

    // FFN
    sgemm_kernel<1><<<gemm_grid_f, TPB>>>(p_h, W1, p_mid, b1, NN, FFND, HIDD);
    sgemm_kernel<2><<<gemm_grid_h, TPB>>>(p_mid, W2, p_agg, b2, NN, HIDD, FFND);

    // out = LN2(h + ffn_out)
    ln_kernel<<<(NN * 32 + TPB - 1) / TPB, TPB>>>(p_agg, p_h, nullptr, ln2g, ln2b, out);
}

// round 4
// speedup vs baseline: 1.7662x; 1.7195x over previous
#include <cuda_runtime.h>
#include <cuda_bf16.h>
#include <math.h>
#include <stdint.h>

#define NN   50000
#define EE   800000
#define ETOT 850000
#define HIDD 256
#define FFND 1024
#define MTILES ((NN + 127) / 128)   // 391

// ---------------- scratch (static device globals; no allocs) ----------------
__device__ float    g_xsrc[(size_t)NN * HIDD];
__device__ float    g_xdst[(size_t)NN * HIDD];
__device__ float    g_h   [(size_t)NN * HIDD];
__device__ float    g_agg [(size_t)NN * HIDD];
__device__ float    g_ssrc[NN * 16];
__device__ float    g_sdst[NN * 16];
__device__ unsigned g_menc[NN * 8];
__device__ float    g_denom[NN * 8];
__device__ float    g_alpha[(size_t)ETOT * 8];
// bf16 split operands
__device__ __nv_bfloat16 g_xh[(size_t)NN * HIDD], g_xl[(size_t)NN * HIDD];
__device__ __nv_bfloat16 g_hh[(size_t)NN * HIDD], g_hl[(size_t)NN * HIDD];
__device__ __nv_bfloat16 g_mh[(size_t)NN * FFND], g_ml[(size_t)NN * FFND];
__device__ __nv_bfloat16 g_wsh[HIDD * HIDD], g_wsl[HIDD * HIDD];
__device__ __nv_bfloat16 g_wdh[HIDD * HIDD], g_wdl[HIDD * HIDD];
__device__ __nv_bfloat16 g_w1h[FFND * HIDD], g_w1l[FFND * HIDD];
__device__ __nv_bfloat16 g_w2h[HIDD * FFND], g_w2l[HIDD * FFND];

// ---------------- small helpers ----------------
__device__ __forceinline__ unsigned fenc(float f) {
    unsigned b = __float_as_uint(f);
    return (b >> 31) ? ~b : (b | 0x80000000u);
}
__device__ __forceinline__ float fdec(unsigned u) {
    return (u >> 31) ? __uint_as_float(u & 0x7fffffffu) : __uint_as_float(~u);
}
__device__ __forceinline__ void red_add_v4(float* p, float a, float b, float c, float d) {
    asm volatile("red.global.add.v4.f32 [%0], {%1,%2,%3,%4};"
                 :: "l"(p), "f"(a), "f"(b), "f"(c), "f"(d) : "memory");
}
__device__ __forceinline__ uint32_t smem_u32(const void* p) {
    uint32_t a;
    asm("{ .reg .u64 t; cvta.to.shared.u64 t, %1; cvt.u32.u64 %0, t; }" : "=r"(a) : "l"(p));
    return a;
}
__device__ __forceinline__ void ldsm4(uint32_t* r, uint32_t addr) {
    asm volatile("ldmatrix.sync.aligned.m8n8.x4.shared.b16 {%0,%1,%2,%3}, [%4];"
                 : "=r"(r[0]), "=r"(r[1]), "=r"(r[2]), "=r"(r[3]) : "r"(addr));
}
__device__ __forceinline__ void mma16816(float* c, const uint32_t* a, const uint32_t* b) {
    asm volatile(
        "mma.sync.aligned.m16n8k16.row.col.f32.bf16.bf16.f32 "
        "{%0,%1,%2,%3}, {%4,%5,%6,%7}, {%8,%9}, {%0,%1,%2,%3};"
        : "+f"(c[0]), "+f"(c[1]), "+f"(c[2]), "+f"(c[3])
        : "r"(a[0]), "r"(a[1]), "r"(a[2]), "r"(a[3]), "r"(b[0]), "r"(b[1]));
}
__device__ __forceinline__ void cp16(uint32_t dst, const void* src, int pred_bytes) {
    asm volatile("cp.async.cg.shared.global [%0], [%1], 16, %2;"
                 :: "r"(dst), "l"(src), "r"(pred_bytes) : "memory");
}

// SMEM stage layout: Ah(128x32 bf16, 80B pitch)=10240, Al, Bh, Bl -> 40960 per stage, x2
#define ROWPITCH 80
#define MAT_BYTES 10240
#define STAGE_BYTES 40960
#define GEMM_SMEM (2 * STAGE_BYTES)

// ---------------- tensor-core GEMM (mma.sync bf16, 3-pass split) ----------------
// C[M,Nd] = A[M,K] * B[Nd,K]^T.  EPI: 0 plain f32; 1 bias+gelu -> bf16 hi/lo; 2 bias -> f32
template<int EPI>
__global__ void __launch_bounds__(256, 1) gemm_tc(
    const __nv_bfloat16* __restrict__ Ah, const __nv_bfloat16* __restrict__ Al,
    const __nv_bfloat16* __restrict__ Bh, const __nv_bfloat16* __restrict__ Bl,
    float* __restrict__ Cf, __nv_bfloat16* __restrict__ Ch, __nv_bfloat16* __restrict__ Cl,
    const float* __restrict__ bias, int M, int Nd, int Kt)
{
    extern __shared__ __align__(128) char smem[];
    const uint32_t sb = smem_u32(smem);
    const int tid = threadIdx.x, wid = tid >> 5, lane = tid & 31;
    const int bm = blockIdx.y * 128, bn = blockIdx.x * 128;
    const int wm = (wid & 1) * 64, wn = (wid >> 1) * 32;

    float acc[4][4][4];
#pragma unroll
    for (int a = 0; a < 4; a++)
#pragma unroll
        for (int b = 0; b < 4; b++)
#pragma unroll
            for (int q = 0; q < 4; q++) acc[a][b][q] = 0.f;

    // per-thread load slots: i = tid + 256*j over 2048 16B chunks
    const int NC = Kt >> 5;

    auto issue_stage = [&](int c) {
        const int k0 = c << 5;
        const uint32_t stb = sb + (c & 1) * STAGE_BYTES;
#pragma unroll
        for (int j = 0; j < 8; j++) {
            int i = tid + (j << 8);
            int mt = i >> 9;            // 0 Ah, 1 Al, 2 Bh, 3 Bl
            int rem = i & 511;
            int row = rem >> 2, ch = rem & 3;
            uint32_t dst = stb + mt * MAT_BYTES + row * ROWPITCH + ch * 16;
            const __nv_bfloat16* src;
            int pb = 16;
            if (mt == 0) {
                int gm = bm + row;
                if (gm >= M) { gm = 0; pb = 0; }
                src = Ah + (size_t)gm * Kt + k0 + ch * 8;
            } else if (mt == 1) {
                int gm = bm + row;
                if (gm >= M) { gm = 0; pb = 0; }
                src = Al + (size_t)gm * Kt + k0 + ch * 8;
            } else if (mt == 2) {
                src = Bh + (size_t)(bn + row) * Kt + k0 + ch * 8;
            } else {
                src = Bl + (size_t)(bn + row) * Kt + k0 + ch * 8;
            }
            cp16(dst, src, pb);
        }
        asm volatile("cp.async.commit_group;" ::: "memory");
    };

    issue_stage(0);
    for (int c = 0; c < NC; c++) {
        if (c + 1 < NC) {
            issue_stage(c + 1);
            asm volatile("cp.async.wait_group 1;" ::: "memory");
        } else {
            asm volatile("cp.async.wait_group 0;" ::: "memory");
        }
        __syncthreads();
        const uint32_t stb = sb + (c & 1) * STAGE_BYTES;
#pragma unroll
        for (int kk = 0; kk < 2; kk++) {
            uint32_t aH[4][4], aL[4][4], bH[2][4], bL[2][4];
            const int arow = wm + (lane & 15);
            const int acol = kk * 32 + (lane >> 4) * 16;
#pragma unroll
            for (int t = 0; t < 4; t++) {
                uint32_t ad = stb + (arow + t * 16) * ROWPITCH + acol;
                ldsm4(aH[t], ad);
                ldsm4(aL[t], ad + MAT_BYTES);
            }
            const int brow = wn + (lane & 7) + ((lane >> 4) << 3);
            const int bcol = kk * 32 + ((lane >> 3) & 1) * 16;
#pragma unroll
            for (int p = 0; p < 2; p++) {
                uint32_t bd = stb + 2 * MAT_BYTES + (brow + p * 16) * ROWPITCH + bcol;
                ldsm4(bH[p], bd);
                ldsm4(bL[p], bd + MAT_BYTES);
            }
#pragma unroll
            for (int tm = 0; tm < 4; tm++)
#pragma unroll
                for (int tn = 0; tn < 4; tn++) {
                    const uint32_t* bh = &bH[tn >> 1][(tn & 1) * 2];
                    const uint32_t* bl = &bL[tn >> 1][(tn & 1) * 2];
                    mma16816(acc[tm][tn], aH[tm], bh);
                    mma16816(acc[tm][tn], aH[tm], bl);
                    mma16816(acc[tm][tn], aL[tm], bh);
                }
        }
        __syncthreads();
    }

    // epilogue
    const int r0 = lane >> 2, c0 = (lane & 3) * 2;
#pragma unroll
    for (int tm = 0; tm < 4; tm++) {
        const int mbase = bm + wm + tm * 16 + r0;
#pragma unroll
        for (int tn = 0; tn < 4; tn++) {
            const int n0 = bn + wn + tn * 8 + c0;
#pragma unroll
            for (int hf = 0; hf < 2; hf++) {
                const int m = mbase + hf * 8;
                if (m >= M) continue;
                float v0 = acc[tm][tn][hf * 2];
                float v1 = acc[tm][tn][hf * 2 + 1];
                if (EPI == 0) {
                    *(float2*)(Cf + (size_t)m * Nd + n0) = make_float2(v0, v1);
                } else if (EPI == 2) {
                    v0 += bias[n0]; v1 += bias[n0 + 1];
                    *(float2*)(Cf + (size_t)m * Nd + n0) = make_float2(v0, v1);
                } else {
                    v0 += bias[n0]; v1 += bias[n0 + 1];
                    v0 = 0.5f * v0 * (1.f + erff(v0 * 0.70710678118654752f));
                    v1 = 0.5f * v1 * (1.f + erff(v1 * 0.70710678118654752f));
                    __nv_bfloat16 h0 = __float2bfloat16(v0);
                    __nv_bfloat16 h1 = __float2bfloat16(v1);
                    __nv_bfloat162 hp; hp.x = h0; hp.y = h1;
                    __nv_bfloat162 lp;
                    lp.x = __float2bfloat16(v0 - __bfloat162float(h0));
                    lp.y = __float2bfloat16(v1 - __bfloat162float(h1));
                    *(__nv_bfloat162*)(Ch + (size_t)m * Nd + n0) = hp;
                    *(__nv_bfloat162*)(Cl + (size_t)m * Nd + n0) = lp;
                }
            }
        }
    }
}

// ---------------- f32 -> bf16 hi/lo split ----------------
__global__ void split_kernel(const float* __restrict__ in, __nv_bfloat16* __restrict__ hi,
                             __nv_bfloat16* __restrict__ lo, int n4) {
    int i = blockIdx.x * blockDim.x + threadIdx.x;
    if (i >= n4) return;
    float4 v = *(const float4*)(in + (size_t)i * 4);
    __nv_bfloat16 h0 = __float2bfloat16(v.x), h1 = __float2bfloat16(v.y);
    __nv_bfloat16 h2 = __float2bfloat16(v.z), h3 = __float2bfloat16(v.w);
    __nv_bfloat162 hp0; hp0.x = h0; hp0.y = h1;
    __nv_bfloat162 hp1; hp1.x = h2; hp1.y = h3;
    __nv_bfloat162 lp0, lp1;
    lp0.x = __float2bfloat16(v.x - __bfloat162float(h0));
    lp0.y = __float2bfloat16(v.y - __bfloat162float(h1));
    lp1.x = __float2bfloat16(v.z - __bfloat162float(h2));
    lp1.y = __float2bfloat16(v.w - __bfloat162float(h3));
    *(__nv_bfloat162*)(hi + (size_t)i * 4)     = hp0;
    *(__nv_bfloat162*)(hi + (size_t)i * 4 + 2) = hp1;
    *(__nv_bfloat162*)(lo + (size_t)i * 4)     = lp0;
    *(__nv_bfloat162*)(lo + (size_t)i * 4 + 2) = lp1;
}

// ---------------- init accumulators ----------------
__global__ void init_kernel() {
    int i = blockIdx.x * blockDim.x + threadIdx.x;
    if (i < NN * HIDD) g_agg[i] = 0.f;
    if (i < NN * 8) { g_menc[i] = 0u; g_denom[i] = 0.f; }
}

// ---------------- per-node attention dots ----------------
__global__ void node_prep_kernel(const float* __restrict__ att_src,
                                 const float* __restrict__ att_dst) {
    int i = blockIdx.x * blockDim.x + threadIdx.x;
    if (i >= NN * 8) return;
    int n = i >> 3, h = i & 7;
    const float4* xs = (const float4*)&g_xsrc[(size_t)n * HIDD + h * 32];
    const float4* xd = (const float4*)&g_xdst[(size_t)n * HIDD + h * 32];
    const float4* as0 = (const float4*)&att_src[h * 32];
    const float4* as1 = (const float4*)&att_src[(8 + h) * 32];
    const float4* ad0 = (const float4*)&att_dst[h * 32];
    const float4* ad1 = (const float4*)&att_dst[(8 + h) * 32];
    float s0 = 0.f, s1 = 0.f, d0 = 0.f, d1 = 0.f;
#pragma unroll
    for (int q = 0; q < 8; q++) {
        float4 a = xs[q], c = xd[q];
        float4 b0 = as0[q], b1 = as1[q], e0 = ad0[q], e1 = ad1[q];
        s0 += a.x * b0.x + a.y * b0.y + a.z * b0.z + a.w * b0.w;
        s1 += a.x * b1.x + a.y * b1.y + a.z * b1.z + a.w * b1.w;
        d0 += c.x * e0.x + c.y * e0.y + c.z * e0.z + c.w * e0.w;
        d1 += c.x * e1.x + c.y * e1.y + c.z * e1.z + c.w * e1.w;
    }
    g_ssrc[n * 16 + h] = s0;
    g_ssrc[n * 16 + 8 + h] = s1;
    g_sdst[n * 16 + h] = d0;
    g_sdst[n * 16 + 8 + h] = d1;
}

// ---------------- edge passes ----------------
__global__ void edgeA_kernel(const int* __restrict__ ei, const int* __restrict__ et) {
    int e = blockIdx.x * blockDim.x + threadIdx.x;
    if (e >= ETOT) return;
    int s, d, t;
    if (e < EE) { s = ei[e]; d = ei[EE + e]; t = et[e]; }
    else        { s = d = e - EE; t = 0; }
    float4 s0 = *(const float4*)&g_ssrc[s * 16 + t * 8];
    float4 s1 = *(const float4*)&g_ssrc[s * 16 + t * 8 + 4];
    float4 d0 = *(const float4*)&g_sdst[d * 16 + t * 8];
    float4 d1 = *(const float4*)&g_sdst[d * 16 + t * 8 + 4];
    float al[8] = { s0.x + d0.x, s0.y + d0.y, s0.z + d0.z, s0.w + d0.w,
                    s1.x + d1.x, s1.y + d1.y, s1.z + d1.z, s1.w + d1.w };
#pragma unroll
    for (int h = 0; h < 8; h++) al[h] = (al[h] >= 0.f) ? al[h] : 0.2f * al[h];
    float* ap = &g_alpha[(size_t)e * 8];
    *(float4*)ap       = make_float4(al[0], al[1], al[2], al[3]);
    *(float4*)(ap + 4) = make_float4(al[4], al[5], al[6], al[7]);
#pragma unroll
    for (int h = 0; h < 8; h++) atomicMax(&g_menc[d * 8 + h], fenc(al[h]));
}

__global__ void edgeB_kernel(const int* __restrict__ ei) {
    int e = blockIdx.x * blockDim.x + threadIdx.x;
    if (e >= ETOT) return;
    int d = (e < EE) ? ei[EE + e] : (e - EE);
    float* ap = &g_alpha[(size_t)e * 8];
    float4 a0 = *(const float4*)ap;
    float4 a1 = *(const float4*)(ap + 4);
    uint4 m0 = *(const uint4*)&g_menc[d * 8];
    uint4 m1 = *(const uint4*)&g_menc[d * 8 + 4];
    float p[8];
    p[0] = expf(a0.x - fdec(m0.x)); p[1] = expf(a0.y - fdec(m0.y));
    p[2] = expf(a0.z - fdec(m0.z)); p[3] = expf(a0.w - fdec(m0.w));
    p[4] = expf(a1.x - fdec(m1.x)); p[5] = expf(a1.y - fdec(m1.y));
    p[6] = expf(a1.z - fdec(m1.z)); p[7] = expf(a1.w - fdec(m1.w));
    *(float4*)ap       = make_float4(p[0], p[1], p[2], p[3]);
    *(float4*)(ap + 4) = make_float4(p[4], p[5], p[6], p[7]);
#pragma unroll
    for (int h = 0; h < 8; h++) atomicAdd(&g_denom[d * 8 + h], p[h]);
}

__global__ void __launch_bounds__(256) edgeC_kernel(const int* __restrict__ ei,
                                                    const float* __restrict__ ew) {
    int e = (blockIdx.x * blockDim.x + threadIdx.x) >> 5;
    int lane = threadIdx.x & 31;
    if (e >= ETOT) return;
    int s, d; float w;
    if (e < EE) { s = ei[e]; d = ei[EE + e]; w = ew[e]; }
    else        { s = d = e - EE; w = 1.f; }
    float cv = 0.f;
    if (lane < 8) cv = g_alpha[(size_t)e * 8 + lane] / g_denom[d * 8 + lane] * w;
    float c1 = __shfl_sync(0xffffffffu, cv, lane >> 3);
    float c2 = __shfl_sync(0xffffffffu, cv, 4 + (lane >> 3));
    const float4* xs = (const float4*)&g_xsrc[(size_t)s * HIDD];
    float4 v1 = xs[lane];
    float4 v2 = xs[32 + lane];
    float* op = &g_agg[(size_t)d * HIDD];
    red_add_v4(op + lane * 4,       v1.x * c1, v1.y * c1, v1.z * c1, v1.w * c1);
    red_add_v4(op + 128 + lane * 4, v2.x * c2, v2.y * c2, v2.z * c2, v2.w * c2);
}

// ---------------- LayerNorm (+ optional fused bf16 split output) ----------------
__global__ void ln_kernel(const float* __restrict__ a, const float* __restrict__ b,
                          const float* __restrict__ colbias,
                          const float* __restrict__ g, const float* __restrict__ beta,
                          float* __restrict__ out,
                          __nv_bfloat16* __restrict__ ohi, __nv_bfloat16* __restrict__ olo) {
    int row = (blockIdx.x * blockDim.x + threadIdx.x) >> 5;
    int lane = threadIdx.x & 31;
    if (row >= NN) return;
    size_t base = (size_t)row * HIDD;
    float4 a0 = *(const float4*)&a[base + lane * 4];
    float4 a1 = *(const float4*)&a[base + 128 + lane * 4];
    float4 b0 = *(const float4*)&b[base + lane * 4];
    float4 b1 = *(const float4*)&b[base + 128 + lane * 4];
    float v[8] = { a0.x + b0.x, a0.y + b0.y, a0.z + b0.z, a0.w + b0.w,
                   a1.x + b1.x, a1.y + b1.y, a1.z + b1.z, a1.w + b1.w };
    if (colbias) {
        float4 c0 = *(const float4*)&colbias[lane * 4];
        float4 c1 = *(const float4*)&colbias[128 + lane * 4];
        v[0] += c0.x; v[1] += c0.y; v[2] += c0.z; v[3] += c0.w;
        v[4] += c1.x; v[5] += c1.y; v[6] += c1.z; v[7] += c1.w;
    }
    float s = 0.f, s2 = 0.f;
#pragma unroll
    for (int q = 0; q < 8; q++) { s += v[q]; s2 += v[q] * v[q]; }
#pragma unroll
    for (int off = 16; off; off >>= 1) {
        s  += __shfl_xor_sync(0xffffffffu, s, off);
        s2 += __shfl_xor_sync(0xffffffffu, s2, off);
    }
    float mu = s * (1.f / 256.f);
    float var = s2 * (1.f / 256.f) - mu * mu;
    float r = rsqrtf(var + 1e-5f);
    float4 g0 = *(const float4*)&g[lane * 4];
    float4 g1 = *(const float4*)&g[128 + lane * 4];
    float4 e0 = *(const float4*)&beta[lane * 4];
    float4 e1 = *(const float4*)&beta[128 + lane * 4];
    float o[8];
    o[0] = (v[0] - mu) * r * g0.x + e0.x; o[1] = (v[1] - mu) * r * g0.y + e0.y;
    o[2] = (v[2] - mu) * r * g0.z + e0.z; o[3] = (v[3] - mu) * r * g0.w + e0.w;
    o[4] = (v[4] - mu) * r * g1.x + e1.x; o[5] = (v[5] - mu) * r * g1.y + e1.y;
    o[6] = (v[6] - mu) * r * g1.z + e1.z; o[7] = (v[7] - mu) * r * g1.w + e1.w;
    *(float4*)&out[base + lane * 4]       = make_float4(o[0], o[1], o[2], o[3]);
    *(float4*)&out[base + 128 + lane * 4] = make_float4(o[4], o[5], o[6], o[7]);
    if (ohi) {
#pragma unroll
        for (int q = 0; q < 8; q += 2) {
            int col = (q < 4) ? (lane * 4 + q) : (128 + lane * 4 + q - 4);
            __nv_bfloat16 h0 = __float2bfloat16(o[q]);
            __nv_bfloat16 h1 = __float2bfloat16(o[q + 1]);
            __nv_bfloat162 hp; hp.x = h0; hp.y = h1;
            __nv_bfloat162 lp;
            lp.x = __float2bfloat16(o[q] - __bfloat162float(h0));
            lp.y = __float2bfloat16(o[q + 1] - __bfloat162float(h1));
            *(__nv_bfloat162*)(ohi + base + col) = hp;
            *(__nv_bfloat162*)(olo + base + col) = lp;
        }
    }
}

// ---------------- launch ----------------
extern "C" void kernel_launch(void* const* d_in, const int* in_sizes, int n_in,
                              void* d_out, int out_size) {
    const float* x       = (const float*)d_in[0];
    const int*   ei      = (const int*)  d_in[1];
    const int*   et      = (const int*)  d_in[2];
    const float* ew      = (const float*)d_in[3];
    const float* Wsrc    = (const float*)d_in[4];
    const float* Wdst    = (const float*)d_in[5];
    const float* att_src = (const float*)d_in[6];
    const float* att_dst = (const float*)d_in[7];
    const float* bias    = (const float*)d_in[8];
    const float* ln1g    = (const float*)d_in[9];
    const float* ln1b    = (const float*)d_in[10];
    const float* ln2g    = (const float*)d_in[11];
    const float* ln2b    = (const float*)d_in[12];
    const float* W1      = (const float*)d_in[13];
    const float* b1      = (const float*)d_in[14];
    const float* W2      = (const float*)d_in[15];
    const float* b2      = (const float*)d_in[16];
    float* out = (float*)d_out;

    float *p_xsrc, *p_xdst, *p_h, *p_agg;
    cudaGetSymbolAddress((void**)&p_xsrc, g_xsrc);
    cudaGetSymbolAddress((void**)&p_xdst, g_xdst);
    cudaGetSymbolAddress((void**)&p_h,    g_h);
    cudaGetSymbolAddress((void**)&p_agg,  g_agg);
    __nv_bfloat16 *p_xh, *p_xl, *p_hh, *p_hl, *p_mh, *p_ml;
    __nv_bfloat16 *p_wsh, *p_wsl, *p_wdh, *p_wdl, *p_w1h, *p_w1l, *p_w2h, *p_w2l;
    cudaGetSymbolAddress((void**)&p_xh, g_xh);   cudaGetSymbolAddress((void**)&p_xl, g_xl);
    cudaGetSymbolAddress((void**)&p_hh, g_hh);   cudaGetSymbolAddress((void**)&p_hl, g_hl);
    cudaGetSymbolAddress((void**)&p_mh, g_mh);   cudaGetSymbolAddress((void**)&p_ml, g_ml);
    cudaGetSymbolAddress((void**)&p_wsh, g_wsh); cudaGetSymbolAddress((void**)&p_wsl, g_wsl);
    cudaGetSymbolAddress((void**)&p_wdh, g_wdh); cudaGetSymbolAddress((void**)&p_wdl, g_wdl);
    cudaGetSymbolAddress((void**)&p_w1h, g_w1h); cudaGetSymbolAddress((void**)&p_w1l, g_w1l);
    cudaGetSymbolAddress((void**)&p_w2h, g_w2h); cudaGetSymbolAddress((void**)&p_w2l, g_w2l);

    cudaFuncSetAttribute(gemm_tc<0>, cudaFuncAttributeMaxDynamicSharedMemorySize, GEMM_SMEM);
    cudaFuncSetAttribute(gemm_tc<1>, cudaFuncAttributeMaxDynamicSharedMemorySize, GEMM_SMEM);
    cudaFuncSetAttribute(gemm_tc<2>, cudaFuncAttributeMaxDynamicSharedMemorySize, GEMM_SMEM);

    const int TPB = 256;
    init_kernel<<<(NN * HIDD + TPB - 1) / TPB, TPB>>>();

    split_kernel<<<(NN * HIDD / 4 + TPB - 1) / TPB, TPB>>>(x, p_xh, p_xl, NN * HIDD / 4);
    split_kernel<<<(HIDD * HIDD / 4 + TPB - 1) / TPB, TPB>>>(Wsrc, p_wsh, p_wsl, HIDD * HIDD / 4);
    split_kernel<<<(HIDD * HIDD / 4 + TPB - 1) / TPB, TPB>>>(Wdst, p_wdh, p_wdl, HIDD * HIDD / 4);
    split_kernel<<<(FFND * HIDD / 4 + TPB - 1) / TPB, TPB>>>(W1, p_w1h, p_w1l, FFND * HIDD / 4);
    split_kernel<<<(HIDD * FFND / 4 + TPB - 1) / TPB, TPB>>>(W2, p_w2h, p_w2l, HIDD * FFND / 4);

    gemm_tc<0><<<dim3(HIDD / 128, MTILES), 256, GEMM_SMEM>>>(
        p_xh, p_xl, p_wsh, p_wsl, p_xsrc, nullptr, nullptr, nullptr, NN, HIDD, HIDD);
    gemm_tc<0><<<dim3(HIDD / 128, MTILES), 256, GEMM_SMEM>>>(
        p_xh, p_xl, p_wdh, p_wdl, p_xdst, nullptr, nullptr, nullptr, NN, HIDD, HIDD);

    node_prep_kernel<<<(NN * 8 + TPB - 1) / TPB, TPB>>>(att_src, att_dst);
    edgeA_kernel<<<(ETOT + TPB - 1) / TPB, TPB>>>(ei, et);
    edgeB_kernel<<<(ETOT + TPB - 1) / TPB, TPB>>>(ei);
    edgeC_kernel<<<((size_t)ETOT * 32 + TPB - 1) / TPB, TPB>>>(ei, ew);

    // h = LN1(agg + bias + x), fused bf16 split for FFN input
    ln_kernel<<<(NN * 32 + TPB - 1) / TPB, TPB>>>(p_agg, x, bias, ln1g, ln1b, p_h, p_hh, p_hl);

    // FFN1: mid = gelu(h @ W1^T + b1) -> bf16 split directly
    gemm_tc<1><<<dim3(FFND / 128, MTILES), 256, GEMM_SMEM>>>(
        p_hh, p_hl, p_w1h, p_w1l, nullptr, p_mh, p_ml, b1, NN, FFND, HIDD);
    // FFN2: agg = mid @ W2^T + b2
    gemm_tc<2><<<dim3(HIDD / 128, MTILES), 256, GEMM_SMEM>>>(
        p_mh, p_ml, p_w2h, p_w2l, p_agg, nullptr, nullptr, b2, NN, HIDD, FFND);

    // out = LN2(h + ffn_out)
    ln_kernel<<<(NN * 32 + TPB - 1) / TPB, TPB>>>(p_agg, p_h, nullptr, ln2g, ln2b, out,
                                                  nullptr, nullptr);
}

// round 5
// speedup vs baseline: 2.0274x; 1.1479x over previous
#include <cuda_runtime.h>
#include <cuda_bf16.h>
#include <math.h>
#include <stdint.h>

#define NN   50000
#define EE   800000
#define ETOT 850000
#define HIDD 256
#define FFND 1024
#define MTILES ((NN + 127) / 128)   // 391

// ---------------- scratch (static device globals; no allocs) ----------------
__device__ float    g_xsrc[(size_t)NN * HIDD];
__device__ float    g_h   [(size_t)NN * HIDD];
__device__ float    g_agg [(size_t)NN * HIDD];
__device__ float    g_ssrc[NN * 16];   // [n][t][h]
__device__ float    g_sdst[NN * 16];
__device__ float    g_denom[NN * 8];
// bf16 split operands
__device__ __nv_bfloat16 g_xh[(size_t)NN * HIDD], g_xl[(size_t)NN * HIDD];
__device__ __nv_bfloat16 g_hh[(size_t)NN * HIDD], g_hl[(size_t)NN * HIDD];
__device__ __nv_bfloat16 g_mh[(size_t)NN * FFND], g_ml[(size_t)NN * FFND];
__device__ __nv_bfloat16 g_wsh[HIDD * HIDD], g_wsl[HIDD * HIDD];
__device__ __nv_bfloat16 g_wdh[HIDD * HIDD], g_wdl[HIDD * HIDD];
__device__ __nv_bfloat16 g_w1h[FFND * HIDD], g_w1l[FFND * HIDD];
__device__ __nv_bfloat16 g_w2h[HIDD * FFND], g_w2l[HIDD * FFND];

// ---------------- small helpers ----------------
__device__ __forceinline__ void red_add_v4(float* p, float a, float b, float c, float d) {
    asm volatile("red.global.add.v4.f32 [%0], {%1,%2,%3,%4};"
                 :: "l"(p), "f"(a), "f"(b), "f"(c), "f"(d) : "memory");
}
__device__ __forceinline__ uint32_t smem_u32(const void* p) {
    uint32_t a;
    asm("{ .reg .u64 t; cvta.to.shared.u64 t, %1; cvt.u32.u64 %0, t; }" : "=r"(a) : "l"(p));
    return a;
}
__device__ __forceinline__ void ldsm4(uint32_t* r, uint32_t addr) {
    asm volatile("ldmatrix.sync.aligned.m8n8.x4.shared.b16 {%0,%1,%2,%3}, [%4];"
                 : "=r"(r[0]), "=r"(r[1]), "=r"(r[2]), "=r"(r[3]) : "r"(addr));
}
__device__ __forceinline__ void mma16816(float* c, const uint32_t* a, const uint32_t* b) {
    asm volatile(
        "mma.sync.aligned.m16n8k16.row.col.f32.bf16.bf16.f32 "
        "{%0,%1,%2,%3}, {%4,%5,%6,%7}, {%8,%9}, {%0,%1,%2,%3};"
        : "+f"(c[0]), "+f"(c[1]), "+f"(c[2]), "+f"(c[3])
        : "r"(a[0]), "r"(a[1]), "r"(a[2]), "r"(a[3]), "r"(b[0]), "r"(b[1]));
}
__device__ __forceinline__ void cp16(uint32_t dst, const void* src, int pred_bytes) {
    asm volatile("cp.async.cg.shared.global [%0], [%1], 16, %2;"
                 :: "r"(dst), "l"(src), "r"(pred_bytes) : "memory");
}

// SMEM stage layout: Ah(128x32 bf16, 80B pitch)=10240, Al, Bh, Bl -> 40960 per stage, x2
#define ROWPITCH 80
#define MAT_BYTES 10240
#define STAGE_BYTES 40960
#define GEMM_SMEM (2 * STAGE_BYTES)

// ---------------- tensor-core GEMM (mma.sync bf16, 3-pass split) ----------------
// C[M,Nd] = A[M,K] * B[Nd,K]^T.
// EPI: 0 f32 store + att dots; 1 bias+gelu -> bf16 hi/lo; 2 bias -> f32; 3 att dots only
template<int EPI>
__global__ void __launch_bounds__(256, 1) gemm_tc(
    const __nv_bfloat16* __restrict__ Ah, const __nv_bfloat16* __restrict__ Al,
    const __nv_bfloat16* __restrict__ Bh, const __nv_bfloat16* __restrict__ Bl,
    float* __restrict__ Cf, __nv_bfloat16* __restrict__ Ch, __nv_bfloat16* __restrict__ Cl,
    const float* __restrict__ bias, const float* __restrict__ att, float* __restrict__ sd,
    int M, int Nd, int Kt)
{
    extern __shared__ __align__(128) char smem[];
    const uint32_t sb = smem_u32(smem);
    const int tid = threadIdx.x, wid = tid >> 5, lane = tid & 31;
    const int bm = blockIdx.y * 128, bn = blockIdx.x * 128;
    const int wm = (wid & 1) * 64, wn = (wid >> 1) * 32;

    float acc[4][4][4];
#pragma unroll
    for (int a = 0; a < 4; a++)
#pragma unroll
        for (int b = 0; b < 4; b++)
#pragma unroll
            for (int q = 0; q < 4; q++) acc[a][b][q] = 0.f;

    const int NC = Kt >> 5;

    auto issue_stage = [&](int c) {
        const int k0 = c << 5;
        const uint32_t stb = sb + (c & 1) * STAGE_BYTES;
#pragma unroll
        for (int j = 0; j < 8; j++) {
            int i = tid + (j << 8);
            int mt = i >> 9;            // 0 Ah, 1 Al, 2 Bh, 3 Bl
            int rem = i & 511;
            int row = rem >> 2, ch = rem & 3;
            uint32_t dst = stb + mt * MAT_BYTES + row * ROWPITCH + ch * 16;
            const __nv_bfloat16* src;
            int pb = 16;
            if (mt == 0) {
                int gm = bm + row;
                if (gm >= M) { gm = 0; pb = 0; }
                src = Ah + (size_t)gm * Kt + k0 + ch * 8;
            } else if (mt == 1) {
                int gm = bm + row;
                if (gm >= M) { gm = 0; pb = 0; }
                src = Al + (size_t)gm * Kt + k0 + ch * 8;
            } else if (mt == 2) {
                src = Bh + (size_t)(bn + row) * Kt + k0 + ch * 8;
            } else {
                src = Bl + (size_t)(bn + row) * Kt + k0 + ch * 8;
            }
            cp16(dst, src, pb);
        }
        asm volatile("cp.async.commit_group;" ::: "memory");
    };

    issue_stage(0);
    for (int c = 0; c < NC; c++) {
        if (c + 1 < NC) {
            issue_stage(c + 1);
            asm volatile("cp.async.wait_group 1;" ::: "memory");
        } else {
            asm volatile("cp.async.wait_group 0;" ::: "memory");
        }
        __syncthreads();
        const uint32_t stb = sb + (c & 1) * STAGE_BYTES;
#pragma unroll
        for (int kk = 0; kk < 2; kk++) {
            uint32_t aH[4][4], aL[4][4], bH[2][4], bL[2][4];
            const int arow = wm + (lane & 15);
            const int acol = kk * 32 + (lane >> 4) * 16;
#pragma unroll
            for (int t = 0; t < 4; t++) {
                uint32_t ad = stb + (arow + t * 16) * ROWPITCH + acol;
                ldsm4(aH[t], ad);
                ldsm4(aL[t], ad + MAT_BYTES);
            }
            const int brow = wn + (lane & 7) + ((lane >> 4) << 3);
            const int bcol = kk * 32 + ((lane >> 3) & 1) * 16;
#pragma unroll
            for (int p = 0; p < 2; p++) {
                uint32_t bd = stb + 2 * MAT_BYTES + (brow + p * 16) * ROWPITCH + bcol;
                ldsm4(bH[p], bd);
                ldsm4(bL[p], bd + MAT_BYTES);
            }
#pragma unroll
            for (int tm = 0; tm < 4; tm++)
#pragma unroll
                for (int tn = 0; tn < 4; tn++) {
                    const uint32_t* bh = &bH[tn >> 1][(tn & 1) * 2];
                    const uint32_t* bl = &bL[tn >> 1][(tn & 1) * 2];
                    mma16816(acc[tm][tn], aH[tm], bh);
                    mma16816(acc[tm][tn], aH[tm], bl);
                    mma16816(acc[tm][tn], aL[tm], bh);
                }
        }
        __syncthreads();
    }

    const int r0 = lane >> 2, c0 = (lane & 3) * 2;

    // fused att dots (EPI 0/3): per warp tile = one head's 32 cols
    if (EPI == 0 || EPI == 3) {
        const int h = ((bn + wn) >> 5) & 7;
        const float* at0 = att + h * 32;         // t = 0
        const float* at1 = att + 256 + h * 32;   // t = 1
        float dt0[8], dt1[8];
#pragma unroll
        for (int q = 0; q < 8; q++) { dt0[q] = 0.f; dt1[q] = 0.f; }
#pragma unroll
        for (int tn = 0; tn < 4; tn++)
#pragma unroll
            for (int j = 0; j < 2; j++) {
                int cidx = tn * 8 + c0 + j;
                float a0 = at0[cidx], a1 = at1[cidx];
#pragma unroll
                for (int tm = 0; tm < 4; tm++)
#pragma unroll
                    for (int hf = 0; hf < 2; hf++) {
                        float v = acc[tm][tn][hf * 2 + j];
                        dt0[tm * 2 + hf] += v * a0;
                        dt1[tm * 2 + hf] += v * a1;
                    }
            }
#pragma unroll
        for (int q = 0; q < 8; q++) {
            dt0[q] += __shfl_xor_sync(0xffffffffu, dt0[q], 1);
            dt0[q] += __shfl_xor_sync(0xffffffffu, dt0[q], 2);
            dt1[q] += __shfl_xor_sync(0xffffffffu, dt1[q], 1);
            dt1[q] += __shfl_xor_sync(0xffffffffu, dt1[q], 2);
        }
        if ((lane & 3) == 0) {
#pragma unroll
            for (int tm = 0; tm < 4; tm++)
#pragma unroll
                for (int hf = 0; hf < 2; hf++) {
                    int m = bm + wm + tm * 16 + hf * 8 + r0;
                    if (m < M) {
                        sd[m * 16 + h]     = dt0[tm * 2 + hf];
                        sd[m * 16 + 8 + h] = dt1[tm * 2 + hf];
                    }
                }
        }
        if (EPI == 3) return;   // dots only, no C store
    }

    // epilogue stores
#pragma unroll
    for (int tm = 0; tm < 4; tm++) {
        const int mbase = bm + wm + tm * 16 + r0;
#pragma unroll
        for (int tn = 0; tn < 4; tn++) {
            const int n0 = bn + wn + tn * 8 + c0;
#pragma unroll
            for (int hf = 0; hf < 2; hf++) {
                const int m = mbase + hf * 8;
                if (m >= M) continue;
                float v0 = acc[tm][tn][hf * 2];
                float v1 = acc[tm][tn][hf * 2 + 1];
                if (EPI == 0) {
                    *(float2*)(Cf + (size_t)m * Nd + n0) = make_float2(v0, v1);
                } else if (EPI == 2) {
                    v0 += bias[n0]; v1 += bias[n0 + 1];
                    *(float2*)(Cf + (size_t)m * Nd + n0) = make_float2(v0, v1);
                } else if (EPI == 1) {
                    v0 += bias[n0]; v1 += bias[n0 + 1];
                    v0 = 0.5f * v0 * (1.f + erff(v0 * 0.70710678118654752f));
                    v1 = 0.5f * v1 * (1.f + erff(v1 * 0.70710678118654752f));
                    __nv_bfloat16 h0 = __float2bfloat16(v0);
                    __nv_bfloat16 h1 = __float2bfloat16(v1);
                    __nv_bfloat162 hp; hp.x = h0; hp.y = h1;
                    __nv_bfloat162 lp;
                    lp.x = __float2bfloat16(v0 - __bfloat162float(h0));
                    lp.y = __float2bfloat16(v1 - __bfloat162float(h1));
                    *(__nv_bfloat162*)(Ch + (size_t)m * Nd + n0) = hp;
                    *(__nv_bfloat162*)(Cl + (size_t)m * Nd + n0) = lp;
                }
            }
        }
    }
}

// ---------------- f32 -> bf16 hi/lo split ----------------
__global__ void split_kernel(const float* __restrict__ in, __nv_bfloat16* __restrict__ hi,
                             __nv_bfloat16* __restrict__ lo, int n4) {
    int i = blockIdx.x * blockDim.x + threadIdx.x;
    if (i >= n4) return;
    float4 v = *(const float4*)(in + (size_t)i * 4);
    __nv_bfloat16 h0 = __float2bfloat16(v.x), h1 = __float2bfloat16(v.y);
    __nv_bfloat16 h2 = __float2bfloat16(v.z), h3 = __float2bfloat16(v.w);
    __nv_bfloat162 hp0; hp0.x = h0; hp0.y = h1;
    __nv_bfloat162 hp1; hp1.x = h2; hp1.y = h3;
    __nv_bfloat162 lp0, lp1;
    lp0.x = __float2bfloat16(v.x - __bfloat162float(h0));
    lp0.y = __float2bfloat16(v.y - __bfloat162float(h1));
    lp1.x = __float2bfloat16(v.z - __bfloat162float(h2));
    lp1.y = __float2bfloat16(v.w - __bfloat162float(h3));
    *(__nv_bfloat162*)(hi + (size_t)i * 4)     = hp0;
    *(__nv_bfloat162*)(hi + (size_t)i * 4 + 2) = hp1;
    *(__nv_bfloat162*)(lo + (size_t)i * 4)     = lp0;
    *(__nv_bfloat162*)(lo + (size_t)i * 4 + 2) = lp1;
}

// ---------------- init accumulators ----------------
__global__ void init_kernel() {
    int i = blockIdx.x * blockDim.x + threadIdx.x;
    if (i < NN * HIDD) g_agg[i] = 0.f;
    if (i < NN * 8) g_denom[i] = 0.f;
}

// ---------------- fused edge pass: alpha -> leaky -> exp -> denom + scatter ----------
__global__ void __launch_bounds__(256) edge_fused(const int* __restrict__ ei,
                                                  const int* __restrict__ et,
                                                  const float* __restrict__ ew) {
    int e = (blockIdx.x * blockDim.x + threadIdx.x) >> 5;
    int lane = threadIdx.x & 31;
    if (e >= ETOT) return;
    int s, d, t; float w;
    if (e < EE) { s = ei[e]; d = ei[EE + e]; t = et[e]; w = ew[e]; }
    else        { s = d = e - EE; t = 0; w = 1.f; }
    float cv = 0.f;
    if (lane < 8) {
        float a = g_ssrc[s * 16 + t * 8 + lane] + g_sdst[d * 16 + t * 8 + lane];
        a = (a >= 0.f) ? a : 0.2f * a;
        float p = __expf(a);
        atomicAdd(&g_denom[d * 8 + lane], p);
        cv = p * w;
    }
    float c1 = __shfl_sync(0xffffffffu, cv, lane >> 3);        // heads 0..3
    float c2 = __shfl_sync(0xffffffffu, cv, 4 + (lane >> 3));  // heads 4..7
    const float4* xs = (const float4*)&g_xsrc[(size_t)s * HIDD];
    float4 v1 = xs[lane];
    float4 v2 = xs[32 + lane];
    float* op = &g_agg[(size_t)d * HIDD];
    red_add_v4(op + lane * 4,       v1.x * c1, v1.y * c1, v1.z * c1, v1.w * c1);
    red_add_v4(op + 128 + lane * 4, v2.x * c2, v2.y * c2, v2.z * c2, v2.w * c2);
}

// ---------------- LayerNorm: out = LN(a[/denom] + b + colbias?), optional bf16 split ----
__global__ void ln_kernel(const float* __restrict__ a, const float* __restrict__ b,
                          const float* __restrict__ colbias, const float* __restrict__ denom,
                          const float* __restrict__ g, const float* __restrict__ beta,
                          float* __restrict__ out,
                          __nv_bfloat16* __restrict__ ohi, __nv_bfloat16* __restrict__ olo) {
    int row = (blockIdx.x * blockDim.x + threadIdx.x) >> 5;
    int lane = threadIdx.x & 31;
    if (row >= NN) return;
    size_t base = (size_t)row * HIDD;
    float4 a0 = *(const float4*)&a[base + lane * 4];
    float4 a1 = *(const float4*)&a[base + 128 + lane * 4];
    float4 b0 = *(const float4*)&b[base + lane * 4];
    float4 b1 = *(const float4*)&b[base + 128 + lane * 4];
    if (denom) {
        float r0 = __frcp_rn(denom[row * 8 + (lane >> 3)]);
        float r1 = __frcp_rn(denom[row * 8 + 4 + (lane >> 3)]);
        a0.x *= r0; a0.y *= r0; a0.z *= r0; a0.w *= r0;
        a1.x *= r1; a1.y *= r1; a1.z *= r1; a1.w *= r1;
    }
    float v[8] = { a0.x + b0.x, a0.y + b0.y, a0.z + b0.z, a0.w + b0.w,
                   a1.x + b1.x, a1.y + b1.y, a1.z + b1.z, a1.w + b1.w };
    if (colbias) {
        float4 c0 = *(const float4*)&colbias[lane * 4];
        float4 c1 = *(const float4*)&colbias[128 + lane * 4];
        v[0] += c0.x; v[1] += c0.y; v[2] += c0.z; v[3] += c0.w;
        v[4] += c1.x; v[5] += c1.y; v[6] += c1.z; v[7] += c1.w;
    }
    float s = 0.f, s2 = 0.f;
#pragma unroll
    for (int q = 0; q < 8; q++) { s += v[q]; s2 += v[q] * v[q]; }
#pragma unroll
    for (int off = 16; off; off >>= 1) {
        s  += __shfl_xor_sync(0xffffffffu, s, off);
        s2 += __shfl_xor_sync(0xffffffffu, s2, off);
    }
    float mu = s * (1.f / 256.f);
    float var = s2 * (1.f / 256.f) - mu * mu;
    float r = rsqrtf(var + 1e-5f);
    float4 g0 = *(const float4*)&g[lane * 4];
    float4 g1 = *(const float4*)&g[128 + lane * 4];
    float4 e0 = *(const float4*)&beta[lane * 4];
    float4 e1 = *(const float4*)&beta[128 + lane * 4];
    float o[8];
    o[0] = (v[0] - mu) * r * g0.x + e0.x; o[1] = (v[1] - mu) * r * g0.y + e0.y;
    o[2] = (v[2] - mu) * r * g0.z + e0.z; o[3] = (v[3] - mu) * r * g0.w + e0.w;
    o[4] = (v[4] - mu) * r * g1.x + e1.x; o[5] = (v[5] - mu) * r * g1.y + e1.y;
    o[6] = (v[6] - mu) * r * g1.z + e1.z; o[7] = (v[7] - mu) * r * g1.w + e1.w;
    *(float4*)&out[base + lane * 4]       = make_float4(o[0], o[1], o[2], o[3]);
    *(float4*)&out[base + 128 + lane * 4] = make_float4(o[4], o[5], o[6], o[7]);
    if (ohi) {
#pragma unroll
        for (int q = 0; q < 8; q += 2) {
            int col = (q < 4) ? (lane * 4 + q) : (128 + lane * 4 + q - 4);
            __nv_bfloat16 h0 = __float2bfloat16(o[q]);
            __nv_bfloat16 h1 = __float2bfloat16(o[q + 1]);
            __nv_bfloat162 hp; hp.x = h0; hp.y = h1;
            __nv_bfloat162 lp;
            lp.x = __float2bfloat16(o[q] - __bfloat162float(h0));
            lp.y = __float2bfloat16(o[q + 1] - __bfloat162float(h1));
            *(__nv_bfloat162*)(ohi + base + col) = hp;
            *(__nv_bfloat162*)(olo + base + col) = lp;
        }
    }
}

// ---------------- launch ----------------
extern "C" void kernel_launch(void* const* d_in, const int* in_sizes, int n_in,
                              void* d_out, int out_size) {
    const float* x       = (const float*)d_in[0];
    const int*   ei      = (const int*)  d_in[1];
    const int*   et      = (const int*)  d_in[2];
    const float* ew      = (const float*)d_in[3];
    const float* Wsrc    = (const float*)d_in[4];
    const float* Wdst    = (const float*)d_in[5];
    const float* att_src = (const float*)d_in[6];
    const float* att_dst = (const float*)d_in[7];
    const float* bias    = (const float*)d_in[8];
    const float* ln1g    = (const float*)d_in[9];
    const float* ln1b    = (const float*)d_in[10];
    const float* ln2g    = (const float*)d_in[11];
    const float* ln2b    = (const float*)d_in[12];
    const float* W1      = (const float*)d_in[13];
    const float* b1      = (const float*)d_in[14];
    const float* W2      = (const float*)d_in[15];
    const float* b2      = (const float*)d_in[16];
    float* out = (float*)d_out;

    float *p_xsrc, *p_h, *p_agg, *p_ssrc, *p_sdst, *p_denom;
    cudaGetSymbolAddress((void**)&p_xsrc, g_xsrc);
    cudaGetSymbolAddress((void**)&p_h,    g_h);
    cudaGetSymbolAddress((void**)&p_agg,  g_agg);
    cudaGetSymbolAddress((void**)&p_ssrc, g_ssrc);
    cudaGetSymbolAddress((void**)&p_sdst, g_sdst);
    cudaGetSymbolAddress((void**)&p_denom, g_denom);
    __nv_bfloat16 *p_xh, *p_xl, *p_hh, *p_hl, *p_mh, *p_ml;
    __nv_bfloat16 *p_wsh, *p_wsl, *p_wdh, *p_wdl, *p_w1h, *p_w1l, *p_w2h, *p_w2l;
    cudaGetSymbolAddress((void**)&p_xh, g_xh);   cudaGetSymbolAddress((void**)&p_xl, g_xl);
    cudaGetSymbolAddress((void**)&p_hh, g_hh);   cudaGetSymbolAddress((void**)&p_hl, g_hl);
    cudaGetSymbolAddress((void**)&p_mh, g_mh);   cudaGetSymbolAddress((void**)&p_ml, g_ml);
    cudaGetSymbolAddress((void**)&p_wsh, g_wsh); cudaGetSymbolAddress((void**)&p_wsl, g_wsl);
    cudaGetSymbolAddress((void**)&p_wdh, g_wdh); cudaGetSymbolAddress((void**)&p_wdl, g_wdl);
    cudaGetSymbolAddress((void**)&p_w1h, g_w1h); cudaGetSymbolAddress((void**)&p_w1l, g_w1l);
    cudaGetSymbolAddress((void**)&p_w2h, g_w2h); cudaGetSymbolAddress((void**)&p_w2l, g_w2l);

    cudaFuncSetAttribute(gemm_tc<0>, cudaFuncAttributeMaxDynamicSharedMemorySize, GEMM_SMEM);
    cudaFuncSetAttribute(gemm_tc<1>, cudaFuncAttributeMaxDynamicSharedMemorySize, GEMM_SMEM);
    cudaFuncSetAttribute(gemm_tc<2>, cudaFuncAttributeMaxDynamicSharedMemorySize, GEMM_SMEM);
    cudaFuncSetAttribute(gemm_tc<3>, cudaFuncAttributeMaxDynamicSharedMemorySize, GEMM_SMEM);

    const int TPB = 256;
    init_kernel<<<(NN * HIDD + TPB - 1) / TPB, TPB>>>();

    split_kernel<<<(NN * HIDD / 4 + TPB - 1) / TPB, TPB>>>(x, p_xh, p_xl, NN * HIDD / 4);
    split_kernel<<<(HIDD * HIDD / 4 + TPB - 1) / TPB, TPB>>>(Wsrc, p_wsh, p_wsl, HIDD * HIDD / 4);
    split_kernel<<<(HIDD * HIDD / 4 + TPB - 1) / TPB, TPB>>>(Wdst, p_wdh, p_wdl, HIDD * HIDD / 4);
    split_kernel<<<(FFND * HIDD / 4 + TPB - 1) / TPB, TPB>>>(W1, p_w1h, p_w1l, FFND * HIDD / 4);
    split_kernel<<<(HIDD * FFND / 4 + TPB - 1) / TPB, TPB>>>(W2, p_w2h, p_w2l, HIDD * FFND / 4);

    // xsrc = x @ Wsrc^T (store f32 + fused att_src dots -> g_ssrc)
    gemm_tc<0><<<dim3(HIDD / 128, MTILES), 256, GEMM_SMEM>>>(
        p_xh, p_xl, p_wsh, p_wsl, p_xsrc, nullptr, nullptr, nullptr, att_src, p_ssrc,
        NN, HIDD, HIDD);
    // xdst dots only (att_dst -> g_sdst), no C store
    gemm_tc<3><<<dim3(HIDD / 128, MTILES), 256, GEMM_SMEM>>>(
        p_xh, p_xl, p_wdh, p_wdl, nullptr, nullptr, nullptr, nullptr, att_dst, p_sdst,
        NN, HIDD, HIDD);

    // single fused edge pass (no segment max; softmax normalization deferred to LN1)
    edge_fused<<<((size_t)ETOT * 32 + TPB - 1) / TPB, TPB>>>(ei, et, ew);

    // h = LN1(agg/denom + bias + x), fused bf16 split for FFN input
    ln_kernel<<<(NN * 32 + TPB - 1) / TPB, TPB>>>(p_agg, x, bias, p_denom,
                                                  ln1g, ln1b, p_h, p_hh, p_hl);

    // FFN1: mid = gelu(h @ W1^T + b1) -> bf16 split directly
    gemm_tc<1><<<dim3(FFND / 128, MTILES), 256, GEMM_SMEM>>>(
        p_hh, p_hl, p_w1h, p_w1l, nullptr, p_mh, p_ml, b1, nullptr, nullptr,
        NN, FFND, HIDD);
    // FFN2: agg = mid @ W2^T + b2
    gemm_tc<2><<<dim3(HIDD / 128, MTILES), 256, GEMM_SMEM>>>(
        p_mh, p_ml, p_w2h, p_w2l, p_agg, nullptr, nullptr, b2, nullptr, nullptr,
        NN, HIDD, FFND);

    // out = LN2(h + ffn_out)
    ln_kernel<<<(NN * 32 + TPB - 1) / TPB, TPB>>>(p_agg, p_h, nullptr, nullptr,
                                                  ln2g, ln2b, out, nullptr, nullptr);
}